// round 10
// baseline (speedup 1.0000x reference)
#include <cuda_runtime.h>
#include <cuda_bf16.h>
#include <cstdint>
#include <math.h>

// Problem dims
#define MB   256
#define RDIM 1025
#define CDIM 1024
#define NSPLIT 4
#define BT   16

// E-stream pipeline config
#define NSTAGE 5
#define SROWS  2
#define SFLOATS (SROWS * CDIM)          // 2048 floats = 8KB per stage

// Scratch (__device__ globals: allocation-free)
static __device__ float g_a[MB * RDIM];
static __device__ float g_part[MB * NSPLIT * CDIM];
static __device__ float g_gemm[MB * CDIM];
static __device__ float g_red[8];

// ---------------- PTX helpers ----------------
__device__ __forceinline__ uint32_t smem_u32(const void* p) {
    uint32_t a;
    asm("{ .reg .u64 t; cvta.to.shared.u64 t, %1; cvt.u32.u64 %0, t; }"
        : "=r"(a) : "l"(p));
    return a;
}

#define MBAR_INIT(addr, cnt) \
    asm volatile("mbarrier.init.shared.b64 [%0], %1;" :: "r"(addr), "r"(cnt) : "memory")

#define MBAR_EXPECT_TX(addr, tx) \
    asm volatile("mbarrier.arrive.expect_tx.shared.b64 _, [%0], %1;" :: "r"(addr), "r"(tx) : "memory")

#define BULK_G2S(dst_smem, src_gmem, bytes, mbar) \
    asm volatile("cp.async.bulk.shared::cluster.global.mbarrier::complete_tx::bytes [%0], [%1], %2, [%3];" \
        :: "r"(dst_smem), "l"(src_gmem), "r"(bytes), "r"(mbar) : "memory")

#define MBAR_WAIT_ACQ(addr, parity) do {                                           \
    asm volatile(                                                                  \
        "{\n\t.reg .pred P1;\n\t"                                                  \
        "WA_%=:\n\t"                                                               \
        "mbarrier.try_wait.parity.acquire.cta.shared::cta.b64 P1, [%0], %1, 0x989680;\n\t" \
        "@P1 bra.uni WD_%=;\n\t"                                                   \
        "bra.uni WA_%=;\n\t"                                                       \
        "WD_%=:\n\t}"                                                              \
        :: "r"(addr), "r"(parity) : "memory");                                     \
} while (0)

// -------------------------------------------------------------------------
// K_pre: g_a[b,i] = x1[b,i] * exp(0.5*logvar_in[i]), x1[b,1024] = 1
// -------------------------------------------------------------------------
__global__ __launch_bounds__(256) void k_pre(const float* __restrict__ x,
                                             const float* __restrict__ lv_in)
{
    int idx = blockIdx.x * 256 + threadIdx.x;
    if (idx >= MB * RDIM) return;
    int b = idx / RDIM;
    int i = idx - b * RDIM;
    float xv = (i < CDIM) ? x[b * CDIM + i] : 1.0f;
    g_a[idx] = xv * __expf(0.5f * lv_in[i]);
}

// -------------------------------------------------------------------------
// K_main: E-stream via cp.async.bulk + full-mbarrier ring.
//   Stage freedom is proven by the per-iteration __syncthreads(): the stage
//   refilled at iteration t (== stage used at t-1) was consumed by ALL
//   threads before the barrier at the end of t-1. No empty barriers needed.
// -------------------------------------------------------------------------
__global__ __launch_bounds__(256) void k_main(const float* __restrict__ E)
{
    __shared__ __align__(16) float buf[NSTAGE * SFLOATS];       // 40 KB
    __shared__ float a_sm[272];                                 // chunk a-values (<=257)
    __shared__ __align__(8) unsigned long long mbar_mem[NSTAGE];

    const int tid = threadIdx.x;
    const int bid = blockIdx.x;
    const int b     = bid / NSPLIT;
    const int chunk = bid - b * NSPLIT;
    const int i0 = (chunk * RDIM) / NSPLIT;
    const int i1 = ((chunk + 1) * RDIM) / NSPLIT;
    const int n  = i1 - i0;                       // 256 or 257
    const int nst = (n + SROWS - 1) / SROWS;      // 128 or 129

    const uint32_t mb   = smem_u32(mbar_mem);     // full[s] at +8s
    const uint32_t bufb = smem_u32(buf);

    if (tid == 0) {
        #pragma unroll
        for (int s = 0; s < NSTAGE; ++s)
            MBAR_INIT(mb + s * 8, 1);             // full: tx-based
    }
    #pragma unroll 1
    for (int idx = tid; idx < n; idx += 256)
        a_sm[idx] = g_a[b * RDIM + i0 + idx];
    __syncthreads();

    const float* gsrc = E + (long long)b * (RDIM * CDIM) + (long long)i0 * CDIM;

    // Prologue: fill stages 0..NSTAGE-2
    if (tid == 0) {
        int np = (nst < NSTAGE - 1) ? nst : (NSTAGE - 1);
        #pragma unroll 1
        for (int s = 0; s < np; ++s) {
            int r0 = s * SROWS;
            int nr = (n - r0 < SROWS) ? (n - r0) : SROWS;
            uint32_t bytes = (uint32_t)nr * CDIM * 4u;
            MBAR_EXPECT_TX(mb + s * 8, bytes);
            BULK_G2S(bufb + (uint32_t)s * (SFLOATS * 4),
                     (const void*)(gsrc + (long long)r0 * CDIM),
                     bytes, mb + s * 8);
        }
    }

    float4 c0 = make_float4(0.f, 0.f, 0.f, 0.f);
    float4 c1 = c0;
    int cs = 0, cph = 0;

    #pragma unroll 1
    for (int t = 0; t < nst; ++t) {
        // refill stage (t + NSTAGE-1) % NSTAGE — free since consumed at t-1
        if (tid == 0) {
            int pt = t + NSTAGE - 1;
            if (pt < nst) {
                int s = pt % NSTAGE;
                int r0 = pt * SROWS;
                int nr = (n - r0 < SROWS) ? (n - r0) : SROWS;
                uint32_t bytes = (uint32_t)nr * CDIM * 4u;
                MBAR_EXPECT_TX(mb + s * 8, bytes);
                BULK_G2S(bufb + (uint32_t)s * (SFLOATS * 4),
                         (const void*)(gsrc + (long long)r0 * CDIM),
                         bytes, mb + s * 8);
            }
        }
        // consume stage t
        MBAR_WAIT_ACQ(mb + cs * 8, cph);
        const float* bp = buf + cs * SFLOATS + (tid << 2);
        int r0 = t * SROWS;
        float a0 = a_sm[r0];
        float4 e0 = *(const float4*)bp;
        c0.x += a0 * e0.x; c0.y += a0 * e0.y;
        c0.z += a0 * e0.z; c0.w += a0 * e0.w;
        if (r0 + 1 < n) {
            float a1 = a_sm[r0 + 1];
            float4 e1 = *(const float4*)(bp + CDIM);
            c1.x += a1 * e1.x; c1.y += a1 * e1.y;
            c1.z += a1 * e1.z; c1.w += a1 * e1.w;
        }
        __syncthreads();
        if (++cs == NSTAGE) { cs = 0; cph ^= 1; }
    }

    float4 r;
    r.x = c0.x + c1.x; r.y = c0.y + c1.y;
    r.z = c0.z + c1.z; r.w = c0.w + c1.w;
    *(float4*)(g_part + (long long)bid * CDIM + (tid << 2)) = r;
}

// -------------------------------------------------------------------------
// K_gemm: g_gemm[b,o] = sum_i x1[b,i]*mu[i,o], 16-batch register tiling.
//         bt==0 blocks also accumulate sum(mu^2) -> g_red[ot]
// -------------------------------------------------------------------------
__global__ __launch_bounds__(256) void k_gemm(const float* __restrict__ mu,
                                              const float* __restrict__ x)
{
    __shared__ __align__(16) float xsm[BT * 128];
    const int tid = threadIdx.x;
    const int g   = blockIdx.x;            // 0..63
    const int bt  = g >> 2;
    const int ot  = g & 3;
    const int b0  = bt * BT;
    const int o   = ot * 256 + tid;

    float acc[BT];
    #pragma unroll
    for (int k = 0; k < BT; ++k) acc[k] = 0.f;
    float musq = 0.f;

    #pragma unroll 1
    for (int ic = 0; ic < RDIM; ic += 128) {
        const int len = min(128, RDIM - ic);
        #pragma unroll 1
        for (int idx = tid; idx < len * BT; idx += 256) {
            int il = idx >> 4;
            int bl = idx & (BT - 1);
            int gi = ic + il;
            xsm[idx] = (gi < CDIM) ? x[(b0 + bl) * CDIM + gi] : 1.0f;
        }
        __syncthreads();

        #pragma unroll 1
        for (int il = 0; il < len; ++il) {
            const float4* xp = (const float4*)(xsm + (il << 4));
            float4 x0 = xp[0], x1v = xp[1], x2 = xp[2], x3 = xp[3];
            float mv = mu[(ic + il) * CDIM + o];
            musq += mv * mv;
            acc[0]  += x0.x  * mv; acc[1]  += x0.y  * mv;
            acc[2]  += x0.z  * mv; acc[3]  += x0.w  * mv;
            acc[4]  += x1v.x * mv; acc[5]  += x1v.y * mv;
            acc[6]  += x1v.z * mv; acc[7]  += x1v.w * mv;
            acc[8]  += x2.x  * mv; acc[9]  += x2.y  * mv;
            acc[10] += x2.z  * mv; acc[11] += x2.w  * mv;
            acc[12] += x3.x  * mv; acc[13] += x3.y  * mv;
            acc[14] += x3.z  * mv; acc[15] += x3.w  * mv;
        }
        __syncthreads();
    }
    #pragma unroll
    for (int k = 0; k < BT; ++k)
        g_gemm[(b0 + k) * CDIM + o] = acc[k];

    if (bt == 0) {
        for (int off = 16; off; off >>= 1)
            musq += __shfl_down_sync(0xffffffffu, musq, off);
        __syncthreads();
        if ((tid & 31) == 0) xsm[tid >> 5] = musq;
        __syncthreads();
        if (tid == 0) {
            float v = 0.f;
            #pragma unroll
            for (int w = 0; w < 8; ++w) v += xsm[w];
            g_red[ot] = v;
        }
    }
}

// -------------------------------------------------------------------------
// K_combine: h[b,o] = gemm[b,o] + exp(0.5*lv_out[o]) * sum_chunk partial
//            block 0 also finalizes D_KL -> out[MB*CDIM]
// -------------------------------------------------------------------------
__global__ __launch_bounds__(256) void k_combine(const float* __restrict__ lv_in,
                                                 const float* __restrict__ lv_out,
                                                 float* __restrict__ out)
{
    const int b = blockIdx.x;
    const int o = threadIdx.x << 2;
    float4 p0 = *(const float4*)(g_part + ((b * NSPLIT + 0) * CDIM) + o);
    float4 p1 = *(const float4*)(g_part + ((b * NSPLIT + 1) * CDIM) + o);
    float4 p2 = *(const float4*)(g_part + ((b * NSPLIT + 2) * CDIM) + o);
    float4 p3 = *(const float4*)(g_part + ((b * NSPLIT + 3) * CDIM) + o);
    float4 gm = *(const float4*)(g_gemm + b * CDIM + o);
    float4 lv = *(const float4*)(lv_out + o);
    float4 r;
    r.x = gm.x + __expf(0.5f * lv.x) * ((p0.x + p1.x) + (p2.x + p3.x));
    r.y = gm.y + __expf(0.5f * lv.y) * ((p0.y + p1.y) + (p2.y + p3.y));
    r.z = gm.z + __expf(0.5f * lv.z) * ((p0.z + p1.z) + (p2.z + p3.z));
    r.w = gm.w + __expf(0.5f * lv.w) * ((p0.w + p1.w) + (p2.w + p3.w));
    *(float4*)(out + b * CDIM + o) = r;

    if (b == 0) {
        const int tid = threadIdx.x;
        float svr = 0.f, slvi = 0.f, svc = 0.f, slvo = 0.f;
        for (int i = tid; i < RDIM; i += 256) {
            float v = lv_in[i];
            svr  += __expf(v);
            slvi += v;
        }
        for (int i = tid; i < CDIM; i += 256) {
            float v = lv_out[i];
            svc  += __expf(v);
            slvo += v;
        }
        __shared__ float sm[4][8];
        float vals[4] = {svr, slvi, svc, slvo};
        #pragma unroll
        for (int k = 0; k < 4; ++k) {
            float v = vals[k];
            for (int off = 16; off; off >>= 1)
                v += __shfl_down_sync(0xffffffffu, v, off);
            if ((tid & 31) == 0) sm[k][tid >> 5] = v;
        }
        __syncthreads();
        if (tid == 0) {
            float tot[4];
            #pragma unroll
            for (int k = 0; k < 4; ++k) {
                float v = 0.f;
                #pragma unroll
                for (int w = 0; w < 8; ++w) v += sm[k][w];
                tot[k] = v;
            }
            float musq = g_red[0] + g_red[1] + g_red[2] + g_red[3];
            float dkl = 0.5f * (tot[0] * tot[2] + musq
                                - (float)RDIM * (float)CDIM
                                - (float)CDIM * tot[1]
                                - (float)RDIM * tot[3]);
            out[MB * CDIM] = dkl;
        }
    }
}

// -------------------------------------------------------------------------
// Launch period = 4 -> ncu's skip-5 lands on k_main (index 5 mod 4 == 1).
// -------------------------------------------------------------------------
extern "C" void kernel_launch(void* const* d_in, const int* in_sizes, int n_in,
                              void* d_out, int out_size)
{
    const float* x      = (const float*)d_in[0];
    const float* mu     = (const float*)d_in[1];
    const float* lv_in  = (const float*)d_in[2];
    const float* lv_out = (const float*)d_in[3];
    const float* E      = (const float*)d_in[4];
    float* out = (float*)d_out;

    k_pre<<<(MB * RDIM + 255) / 256, 256>>>(x, lv_in);
    k_main<<<MB * NSPLIT, 256>>>(E);
    k_gemm<<<(MB / BT) * (CDIM / 256), 256>>>(mu, x);
    k_combine<<<MB, 256>>>(lv_in, lv_out, out);
}

// round 12
// speedup vs baseline: 1.0062x; 1.0062x over previous
#include <cuda_runtime.h>
#include <cuda_bf16.h>
#include <math.h>

// Problem dims
#define MB   256
#define RDIM 1025
#define CDIM 1024
#define NSPLIT 8
#define BT   16

// Scratch (__device__ globals: allocation-free)
static __device__ float g_a[MB * RDIM];
static __device__ float g_part[MB * NSPLIT * CDIM];
static __device__ float g_gemm[MB * CDIM];
static __device__ float g_red[8];

// -------------------------------------------------------------------------
// K_pre: g_a[b,i] = x1[b,i] * exp(0.5*logvar_in[i]), x1[b,1024] = 1
// -------------------------------------------------------------------------
__global__ __launch_bounds__(256) void k_pre(const float* __restrict__ x,
                                             const float* __restrict__ lv_in)
{
    int idx = blockIdx.x * 256 + threadIdx.x;
    if (idx >= MB * RDIM) return;
    int b = idx / RDIM;
    int i = idx - b * RDIM;
    float xv = (i < CDIM) ? x[b * CDIM + i] : 1.0f;
    g_a[idx] = xv * __expf(0.5f * lv_in[i]);
}

// -------------------------------------------------------------------------
// K_main: E-stream, plain LDG.128, lean registers, 2048 blocks.
//   block (b,chunk): partial[b,chunk,o] = sum_{i in chunk} a[b,i]*E[b,i,o]
// -------------------------------------------------------------------------
__global__ __launch_bounds__(256) void k_main(const float* __restrict__ E)
{
    __shared__ float a_sm[144];                   // chunk a-values (<=129)

    const int tid = threadIdx.x;
    const int bid = blockIdx.x;
    const int b     = bid >> 3;                   // bid / NSPLIT
    const int chunk = bid & 7;
    const int i0 = (chunk * RDIM) / NSPLIT;
    const int i1 = ((chunk + 1) * RDIM) / NSPLIT;
    const int n  = i1 - i0;                       // 128 or 129

    #pragma unroll 1
    for (int idx = tid; idx < n; idx += 256)
        a_sm[idx] = g_a[b * RDIM + i0 + idx];
    __syncthreads();

    // float4 view; row stride = 256 float4
    const float4* __restrict__ Ep =
        (const float4*)(E + (long long)b * (RDIM * CDIM)
                          + (long long)i0 * CDIM) + tid;

    float4 c0 = make_float4(0.f, 0.f, 0.f, 0.f);
    float4 c1 = c0;

    int i = 0;
    #pragma unroll 1
    for (; i + 4 <= n; i += 4) {
        float4 e0 = Ep[0];
        float4 e1 = Ep[256];
        float4 e2 = Ep[512];
        float4 e3 = Ep[768];
        float a0 = a_sm[i], a1 = a_sm[i + 1], a2 = a_sm[i + 2], a3 = a_sm[i + 3];
        c0.x += a0*e0.x; c0.y += a0*e0.y; c0.z += a0*e0.z; c0.w += a0*e0.w;
        c1.x += a1*e1.x; c1.y += a1*e1.y; c1.z += a1*e1.z; c1.w += a1*e1.w;
        c0.x += a2*e2.x; c0.y += a2*e2.y; c0.z += a2*e2.z; c0.w += a2*e2.w;
        c1.x += a3*e3.x; c1.y += a3*e3.y; c1.z += a3*e3.z; c1.w += a3*e3.w;
        Ep += 1024;
    }
    #pragma unroll 1
    for (; i < n; ++i) {
        float4 e0 = Ep[0];
        float a0 = a_sm[i];
        c0.x += a0*e0.x; c0.y += a0*e0.y; c0.z += a0*e0.z; c0.w += a0*e0.w;
        Ep += 256;
    }
    float4 r;
    r.x = c0.x + c1.x; r.y = c0.y + c1.y;
    r.z = c0.z + c1.z; r.w = c0.w + c1.w;
    *(float4*)(g_part + (long long)bid * CDIM + (tid << 2)) = r;
}

// -------------------------------------------------------------------------
// K_gemm: g_gemm[b,o] = sum_i x1[b,i]*mu[i,o], 16-batch register tiling.
//         bt==0 blocks also accumulate sum(mu^2) -> g_red[ot]
// -------------------------------------------------------------------------
__global__ __launch_bounds__(256) void k_gemm(const float* __restrict__ mu,
                                              const float* __restrict__ x)
{
    __shared__ __align__(16) float xsm[BT * 128];
    const int tid = threadIdx.x;
    const int g   = blockIdx.x;            // 0..63
    const int bt  = g >> 2;
    const int ot  = g & 3;
    const int b0  = bt * BT;
    const int o   = ot * 256 + tid;

    float acc[BT];
    #pragma unroll
    for (int k = 0; k < BT; ++k) acc[k] = 0.f;
    float musq = 0.f;

    #pragma unroll 1
    for (int ic = 0; ic < RDIM; ic += 128) {
        const int len = min(128, RDIM - ic);
        #pragma unroll 1
        for (int idx = tid; idx < len * BT; idx += 256) {
            int il = idx >> 4;
            int bl = idx & (BT - 1);
            int gi = ic + il;
            xsm[idx] = (gi < CDIM) ? x[(b0 + bl) * CDIM + gi] : 1.0f;
        }
        __syncthreads();

        #pragma unroll 1
        for (int il = 0; il < len; ++il) {
            const float4* xp = (const float4*)(xsm + (il << 4));
            float4 x0 = xp[0], x1v = xp[1], x2 = xp[2], x3 = xp[3];
            float mv = mu[(ic + il) * CDIM + o];
            musq += mv * mv;
            acc[0]  += x0.x  * mv; acc[1]  += x0.y  * mv;
            acc[2]  += x0.z  * mv; acc[3]  += x0.w  * mv;
            acc[4]  += x1v.x * mv; acc[5]  += x1v.y * mv;
            acc[6]  += x1v.z * mv; acc[7]  += x1v.w * mv;
            acc[8]  += x2.x  * mv; acc[9]  += x2.y  * mv;
            acc[10] += x2.z  * mv; acc[11] += x2.w  * mv;
            acc[12] += x3.x  * mv; acc[13] += x3.y  * mv;
            acc[14] += x3.z  * mv; acc[15] += x3.w  * mv;
        }
        __syncthreads();
    }
    #pragma unroll
    for (int k = 0; k < BT; ++k)
        g_gemm[(b0 + k) * CDIM + o] = acc[k];

    if (bt == 0) {
        for (int off = 16; off; off >>= 1)
            musq += __shfl_down_sync(0xffffffffu, musq, off);
        __syncthreads();
        if ((tid & 31) == 0) xsm[tid >> 5] = musq;
        __syncthreads();
        if (tid == 0) {
            float v = 0.f;
            #pragma unroll
            for (int w = 0; w < 8; ++w) v += xsm[w];
            g_red[ot] = v;
        }
    }
}

// -------------------------------------------------------------------------
// K_combine: h[b,o] = gemm[b,o] + exp(0.5*lv_out[o]) * sum_chunk partial
//            block 0 also finalizes D_KL -> out[MB*CDIM]
// -------------------------------------------------------------------------
__global__ __launch_bounds__(256) void k_combine(const float* __restrict__ lv_in,
                                                 const float* __restrict__ lv_out,
                                                 float* __restrict__ out)
{
    const int b = blockIdx.x;
    const int o = threadIdx.x << 2;

    float4 s = make_float4(0.f, 0.f, 0.f, 0.f);
    #pragma unroll
    for (int c = 0; c < NSPLIT; ++c) {
        float4 p = *(const float4*)(g_part + ((b * NSPLIT + c) * CDIM) + o);
        s.x += p.x; s.y += p.y; s.z += p.z; s.w += p.w;
    }
    float4 gm = *(const float4*)(g_gemm + b * CDIM + o);
    float4 lv = *(const float4*)(lv_out + o);
    float4 r;
    r.x = gm.x + __expf(0.5f * lv.x) * s.x;
    r.y = gm.y + __expf(0.5f * lv.y) * s.y;
    r.z = gm.z + __expf(0.5f * lv.z) * s.z;
    r.w = gm.w + __expf(0.5f * lv.w) * s.w;
    *(float4*)(out + b * CDIM + o) = r;

    if (b == 0) {
        const int tid = threadIdx.x;
        float svr = 0.f, slvi = 0.f, svc = 0.f, slvo = 0.f;
        for (int i = tid; i < RDIM; i += 256) {
            float v = lv_in[i];
            svr  += __expf(v);
            slvi += v;
        }
        for (int i = tid; i < CDIM; i += 256) {
            float v = lv_out[i];
            svc  += __expf(v);
            slvo += v;
        }
        __shared__ float sm[4][8];
        float vals[4] = {svr, slvi, svc, slvo};
        #pragma unroll
        for (int k = 0; k < 4; ++k) {
            float v = vals[k];
            for (int off = 16; off; off >>= 1)
                v += __shfl_down_sync(0xffffffffu, v, off);
            if ((tid & 31) == 0) sm[k][tid >> 5] = v;
        }
        __syncthreads();
        if (tid == 0) {
            float tot[4];
            #pragma unroll
            for (int k = 0; k < 4; ++k) {
                float v = 0.f;
                #pragma unroll
                for (int w = 0; w < 8; ++w) v += sm[k][w];
                tot[k] = v;
            }
            float musq = g_red[0] + g_red[1] + g_red[2] + g_red[3];
            float dkl = 0.5f * (tot[0] * tot[2] + musq
                                - (float)RDIM * (float)CDIM
                                - (float)CDIM * tot[1]
                                - (float)RDIM * tot[3]);
            out[MB * CDIM] = dkl;
        }
    }
}

// -------------------------------------------------------------------------
// Launch period = 4 -> ncu's skip-5 lands on k_main (index 5 mod 4 == 1).
// -------------------------------------------------------------------------
extern "C" void kernel_launch(void* const* d_in, const int* in_sizes, int n_in,
                              void* d_out, int out_size)
{
    const float* x      = (const float*)d_in[0];
    const float* mu     = (const float*)d_in[1];
    const float* lv_in  = (const float*)d_in[2];
    const float* lv_out = (const float*)d_in[3];
    const float* E      = (const float*)d_in[4];
    float* out = (float*)d_out;

    k_pre<<<(MB * RDIM + 255) / 256, 256>>>(x, lv_in);
    k_main<<<MB * NSPLIT, 256>>>(E);
    k_gemm<<<(MB / BT) * (CDIM / 256), 256>>>(mu, x);
    k_combine<<<MB, 256>>>(lv_in, lv_out, out);
}

// round 13
// speedup vs baseline: 2.2175x; 2.2038x over previous
#include <cuda_runtime.h>
#include <math.h>

// Problem dims
#define MB     256
#define RDIM   1025
#define CDIM   1024
#define NSPLIT 8
#define BT     16
#define NGEMM  64                 // (MB/BT) * (CDIM/256)
#define TARGET (NSPLIT + 4)       // writers per batch-row b per call

// Scratch (__device__ globals: allocation-free)
static __device__ float g_part[MB * NSPLIT * CDIM];
static __device__ float g_gemm[MB * CDIM];
static __device__ float g_red[4];
static __device__ unsigned int g_cnt[MB];   // monotonic, never reset
static __device__ unsigned int g_cnt2;      // dkl writers counter

// h[b, o..o+3] = gemm + exp(0.5*lv_out)*sum_chunks(part)
__device__ __forceinline__ void write_h(int b, int tid,
                                        const float* __restrict__ lv_out,
                                        float* __restrict__ out)
{
    const int o = tid << 2;
    float4 s = make_float4(0.f, 0.f, 0.f, 0.f);
    #pragma unroll
    for (int c = 0; c < NSPLIT; ++c) {
        float4 p = *(const float4*)(g_part + ((b * NSPLIT + c) * CDIM) + o);
        s.x += p.x; s.y += p.y; s.z += p.z; s.w += p.w;
    }
    float4 gm = *(const float4*)(g_gemm + b * CDIM + o);
    float4 lv = *(const float4*)(lv_out + o);
    float4 r;
    r.x = gm.x + __expf(0.5f * lv.x) * s.x;
    r.y = gm.y + __expf(0.5f * lv.y) * s.y;
    r.z = gm.z + __expf(0.5f * lv.z) * s.z;
    r.w = gm.w + __expf(0.5f * lv.w) * s.w;
    *(float4*)(out + b * CDIM + o) = r;
}

// -------------------------------------------------------------------------
// Single fused kernel.
//   blocks [0, NGEMM):       GEMM role (+ mu^2 partials, + dkl finalize)
//   blocks [NGEMM, +MB*8):   E-stream role
//   last of the 12 writers touching batch-row b emits h[b,:].
// -------------------------------------------------------------------------
__global__ __launch_bounds__(256) void k_all(const float* __restrict__ E,
                                             const float* __restrict__ mu,
                                             const float* __restrict__ x,
                                             const float* __restrict__ lv_in,
                                             const float* __restrict__ lv_out,
                                             float* __restrict__ out)
{
    __shared__ __align__(16) float sm[BT * 128];   // 8 KB, role-dependent use
    __shared__ unsigned int s_mask;
    __shared__ unsigned int s_flag;
    const int tid = threadIdx.x;
    const int bid = blockIdx.x;

    if (bid < NGEMM) {
        // ================= GEMM role =================
        const int bt = bid >> 2;            // 0..15
        const int ot = bid & 3;             // 0..3
        const int b0 = bt * BT;
        const int o  = ot * 256 + tid;

        float acc[BT];
        #pragma unroll
        for (int k = 0; k < BT; ++k) acc[k] = 0.f;
        float musq = 0.f;

        #pragma unroll 1
        for (int ic = 0; ic < RDIM; ic += 128) {
            const int len = min(128, RDIM - ic);
            #pragma unroll 1
            for (int idx = tid; idx < len * BT; idx += 256) {
                int il = idx >> 4;
                int bl = idx & (BT - 1);
                int gi = ic + il;
                sm[idx] = (gi < CDIM) ? x[(b0 + bl) * CDIM + gi] : 1.0f;
            }
            __syncthreads();

            int il = 0;
            #pragma unroll 1
            for (; il + 4 <= len; il += 4) {
                // 4 independent mu loads in flight
                float mv0 = mu[(ic + il    ) * CDIM + o];
                float mv1 = mu[(ic + il + 1) * CDIM + o];
                float mv2 = mu[(ic + il + 2) * CDIM + o];
                float mv3 = mu[(ic + il + 3) * CDIM + o];
                musq += mv0*mv0 + mv1*mv1 + mv2*mv2 + mv3*mv3;
                #pragma unroll
                for (int r = 0; r < 4; ++r) {
                    float mv = (r == 0) ? mv0 : (r == 1) ? mv1 : (r == 2) ? mv2 : mv3;
                    const float4* xp = (const float4*)(sm + ((il + r) << 4));
                    float4 x0 = xp[0], x1v = xp[1], x2 = xp[2], x3 = xp[3];
                    acc[0]  += x0.x  * mv; acc[1]  += x0.y  * mv;
                    acc[2]  += x0.z  * mv; acc[3]  += x0.w  * mv;
                    acc[4]  += x1v.x * mv; acc[5]  += x1v.y * mv;
                    acc[6]  += x1v.z * mv; acc[7]  += x1v.w * mv;
                    acc[8]  += x2.x  * mv; acc[9]  += x2.y  * mv;
                    acc[10] += x2.z  * mv; acc[11] += x2.w  * mv;
                    acc[12] += x3.x  * mv; acc[13] += x3.y  * mv;
                    acc[14] += x3.z  * mv; acc[15] += x3.w  * mv;
                }
            }
            #pragma unroll 1
            for (; il < len; ++il) {
                float mv = mu[(ic + il) * CDIM + o];
                musq += mv * mv;
                const float4* xp = (const float4*)(sm + (il << 4));
                float4 x0 = xp[0], x1v = xp[1], x2 = xp[2], x3 = xp[3];
                acc[0]  += x0.x  * mv; acc[1]  += x0.y  * mv;
                acc[2]  += x0.z  * mv; acc[3]  += x0.w  * mv;
                acc[4]  += x1v.x * mv; acc[5]  += x1v.y * mv;
                acc[6]  += x1v.z * mv; acc[7]  += x1v.w * mv;
                acc[8]  += x2.x  * mv; acc[9]  += x2.y  * mv;
                acc[10] += x2.z  * mv; acc[11] += x2.w  * mv;
                acc[12] += x3.x  * mv; acc[13] += x3.y  * mv;
                acc[14] += x3.z  * mv; acc[15] += x3.w  * mv;
            }
            __syncthreads();
        }
        #pragma unroll
        for (int k = 0; k < BT; ++k)
            g_gemm[(b0 + k) * CDIM + o] = acc[k];

        // mu^2 partial (bt==0 blocks cover mu exactly once)
        if (bt == 0) {
            for (int off = 16; off; off >>= 1)
                musq += __shfl_down_sync(0xffffffffu, musq, off);
            __syncthreads();
            if ((tid & 31) == 0) sm[tid >> 5] = musq;
            __syncthreads();
            if (tid == 0) {
                float v = 0.f;
                #pragma unroll
                for (int w = 0; w < 8; ++w) v += sm[w];
                g_red[ot] = v;
            }
        }

        // publish + count the 16 batch rows this block completed
        __threadfence();
        __syncthreads();
        if (tid == 0) {
            unsigned int m = 0;
            #pragma unroll
            for (int k = 0; k < BT; ++k) {
                unsigned int old = atomicAdd(&g_cnt[b0 + k], 1u);
                if ((old + 1u) % TARGET == 0u) m |= (1u << k);
            }
            s_mask = m;
        }
        __syncthreads();
        {
            unsigned int m = s_mask;
            if (m) {
                __threadfence();
                #pragma unroll 1
                for (int k = 0; k < BT; ++k)
                    if ((m >> k) & 1u) write_h(b0 + k, tid, lv_out, out);
            }
        }

        // D_KL: last of the 4 bt==0 blocks finalizes
        if (bt == 0) {
            if (tid == 0) {
                unsigned int old2 = atomicAdd(&g_cnt2, 1u);
                s_flag = (((old2 + 1u) & 3u) == 0u) ? 1u : 0u;
            }
            __syncthreads();
            if (s_flag) {
                __threadfence();
                float svr = 0.f, slvi = 0.f, svc = 0.f, slvo = 0.f;
                for (int i = tid; i < RDIM; i += 256) {
                    float v = lv_in[i];
                    svr  += __expf(v);
                    slvi += v;
                }
                for (int i = tid; i < CDIM; i += 256) {
                    float v = lv_out[i];
                    svc  += __expf(v);
                    slvo += v;
                }
                float vals[4] = {svr, slvi, svc, slvo};
                __syncthreads();
                #pragma unroll
                for (int k = 0; k < 4; ++k) {
                    float v = vals[k];
                    for (int off = 16; off; off >>= 1)
                        v += __shfl_down_sync(0xffffffffu, v, off);
                    if ((tid & 31) == 0) sm[k * 8 + (tid >> 5)] = v;
                }
                __syncthreads();
                if (tid == 0) {
                    float tot[4];
                    #pragma unroll
                    for (int k = 0; k < 4; ++k) {
                        float v = 0.f;
                        #pragma unroll
                        for (int w = 0; w < 8; ++w) v += sm[k * 8 + w];
                        tot[k] = v;
                    }
                    float musq_t = g_red[0] + g_red[1] + g_red[2] + g_red[3];
                    float dkl = 0.5f * (tot[0] * tot[2] + musq_t
                                        - (float)RDIM * (float)CDIM
                                        - (float)CDIM * tot[1]
                                        - (float)RDIM * tot[3]);
                    out[MB * CDIM] = dkl;
                }
            }
        }
    } else {
        // ================= E-stream role =================
        const int eid   = bid - NGEMM;
        const int b     = eid >> 3;
        const int chunk = eid & 7;
        const int i0 = (chunk * RDIM) / NSPLIT;
        const int i1 = ((chunk + 1) * RDIM) / NSPLIT;
        const int n  = i1 - i0;                       // 128 or 129

        // a[i] = x1[b,i0+i] * exp(0.5*lv_in[i0+i])
        #pragma unroll 1
        for (int idx = tid; idx < n; idx += 256) {
            int gi = i0 + idx;
            float xv = (gi < CDIM) ? x[b * CDIM + gi] : 1.0f;
            sm[idx] = xv * __expf(0.5f * lv_in[gi]);
        }
        __syncthreads();

        const float4* __restrict__ Ep =
            (const float4*)(E + (long long)b * (RDIM * CDIM)
                              + (long long)i0 * CDIM) + tid;

        float4 c0 = make_float4(0.f, 0.f, 0.f, 0.f);
        float4 c1 = c0;

        int i = 0;
        #pragma unroll 1
        for (; i + 4 <= n; i += 4) {
            float4 e0 = Ep[0];
            float4 e1 = Ep[256];
            float4 e2 = Ep[512];
            float4 e3 = Ep[768];
            float a0 = sm[i], a1 = sm[i + 1], a2 = sm[i + 2], a3 = sm[i + 3];
            c0.x += a0*e0.x; c0.y += a0*e0.y; c0.z += a0*e0.z; c0.w += a0*e0.w;
            c1.x += a1*e1.x; c1.y += a1*e1.y; c1.z += a1*e1.z; c1.w += a1*e1.w;
            c0.x += a2*e2.x; c0.y += a2*e2.y; c0.z += a2*e2.z; c0.w += a2*e2.w;
            c1.x += a3*e3.x; c1.y += a3*e3.y; c1.z += a3*e3.z; c1.w += a3*e3.w;
            Ep += 1024;
        }
        #pragma unroll 1
        for (; i < n; ++i) {
            float4 e0 = Ep[0];
            float a0 = sm[i];
            c0.x += a0*e0.x; c0.y += a0*e0.y; c0.z += a0*e0.z; c0.w += a0*e0.w;
            Ep += 256;
        }
        float4 r;
        r.x = c0.x + c1.x; r.y = c0.y + c1.y;
        r.z = c0.z + c1.z; r.w = c0.w + c1.w;
        *(float4*)(g_part + (long long)eid * CDIM + (tid << 2)) = r;

        // publish + count; last of 12 writers emits h[b,:]
        __threadfence();
        __syncthreads();
        if (tid == 0) {
            unsigned int old = atomicAdd(&g_cnt[b], 1u);
            s_flag = ((old + 1u) % TARGET == 0u) ? 1u : 0u;
        }
        __syncthreads();
        if (s_flag) {
            __threadfence();
            write_h(b, tid, lv_out, out);
        }
    }
}

// -------------------------------------------------------------------------
extern "C" void kernel_launch(void* const* d_in, const int* in_sizes, int n_in,
                              void* d_out, int out_size)
{
    const float* x      = (const float*)d_in[0];   // (256, 1024)
    const float* mu     = (const float*)d_in[1];   // (1025, 1024)
    const float* lv_in  = (const float*)d_in[2];   // (1025,)
    const float* lv_out = (const float*)d_in[3];   // (1024,)
    const float* E      = (const float*)d_in[4];   // (256, 1025, 1024)
    float* out = (float*)d_out;                    // (256*1024 h) + 1 scalar

    k_all<<<NGEMM + MB * NSPLIT, 256>>>(E, mu, x, lv_in, lv_out, out);
}

// round 15
// speedup vs baseline: 3.4583x; 1.5596x over previous
#include <cuda_runtime.h>
#include <math.h>

// Problem dims
#define MB     256
#define RDIM   1025
#define CDIM   1024
#define NSPLIT 8
#define BT     8
#define NGEMM  ((MB / BT) * (CDIM / 256))   // 128
#define TARGET (NSPLIT + 4)                 // writers per batch-row b per call

// Scratch (__device__ globals: allocation-free)
static __device__ float g_part[MB * NSPLIT * CDIM];
static __device__ float g_gemm[MB * CDIM];
static __device__ float g_red[4];
static __device__ unsigned int g_cnt[MB];   // monotonic, never reset
static __device__ unsigned int g_cnt2;      // dkl writers counter

// h[b, o..o+3] = gemm + exp(0.5*lv_out)*sum_chunks(part)
__device__ __forceinline__ void write_h(int b, int tid,
                                        const float* __restrict__ lv_out,
                                        float* __restrict__ out)
{
    const int o = tid << 2;
    float4 s = make_float4(0.f, 0.f, 0.f, 0.f);
    #pragma unroll
    for (int c = 0; c < NSPLIT; ++c) {
        float4 p = *(const float4*)(g_part + ((b * NSPLIT + c) * CDIM) + o);
        s.x += p.x; s.y += p.y; s.z += p.z; s.w += p.w;
    }
    float4 gm = *(const float4*)(g_gemm + b * CDIM + o);
    float4 lv = *(const float4*)(lv_out + o);
    float4 r;
    r.x = gm.x + __expf(0.5f * lv.x) * s.x;
    r.y = gm.y + __expf(0.5f * lv.y) * s.y;
    r.z = gm.z + __expf(0.5f * lv.z) * s.z;
    r.w = gm.w + __expf(0.5f * lv.w) * s.w;
    *(float4*)(out + b * CDIM + o) = r;
}

// -------------------------------------------------------------------------
// Single fused kernel, 7 CTAs/SM.
//   blocks [0, NGEMM):       GEMM role (BT=8) + mu^2 partials + dkl finalize
//   blocks [NGEMM, +MB*8):   E-stream role (2-row double-buffered LDG.128)
//   last of the 12 writers touching batch-row b emits h[b,:].
// -------------------------------------------------------------------------
__global__ __launch_bounds__(256, 7) void k_all(const float* __restrict__ E,
                                                const float* __restrict__ mu,
                                                const float* __restrict__ x,
                                                const float* __restrict__ lv_in,
                                                const float* __restrict__ lv_out,
                                                float* __restrict__ out)
{
    __shared__ __align__(16) float sm[1024];   // 4 KB, role-dependent use
    __shared__ unsigned int s_mask;
    __shared__ unsigned int s_flag;
    const int tid = threadIdx.x;
    const int bid = blockIdx.x;

    if (bid < NGEMM) {
        // ================= GEMM role (BT = 8) =================
        const int bt = bid >> 2;            // 0..31
        const int ot = bid & 3;             // 0..3
        const int b0 = bt * BT;
        const int o  = ot * 256 + tid;

        float acc[BT];
        #pragma unroll
        for (int k = 0; k < BT; ++k) acc[k] = 0.f;
        float musq = 0.f;

        #pragma unroll 1
        for (int ic = 0; ic < RDIM; ic += 128) {
            const int len = min(128, RDIM - ic);
            // xsm[il*8 + bl] = x1[b0+bl, ic+il]
            #pragma unroll 1
            for (int idx = tid; idx < len * BT; idx += 256) {
                int il = idx >> 3;
                int bl = idx & 7;
                int gi = ic + il;
                sm[idx] = (gi < CDIM) ? x[(b0 + bl) * CDIM + gi] : 1.0f;
            }
            __syncthreads();

            int il = 0;
            #pragma unroll 1
            for (; il + 4 <= len; il += 4) {
                float mv0 = mu[(ic + il    ) * CDIM + o];
                float mv1 = mu[(ic + il + 1) * CDIM + o];
                float mv2 = mu[(ic + il + 2) * CDIM + o];
                float mv3 = mu[(ic + il + 3) * CDIM + o];
                musq += mv0*mv0 + mv1*mv1 + mv2*mv2 + mv3*mv3;
                #pragma unroll
                for (int r = 0; r < 4; ++r) {
                    float mv = (r == 0) ? mv0 : (r == 1) ? mv1 : (r == 2) ? mv2 : mv3;
                    const float4* xp = (const float4*)(sm + ((il + r) << 3));
                    float4 x0 = xp[0], x1v = xp[1];
                    acc[0] += x0.x  * mv; acc[1] += x0.y  * mv;
                    acc[2] += x0.z  * mv; acc[3] += x0.w  * mv;
                    acc[4] += x1v.x * mv; acc[5] += x1v.y * mv;
                    acc[6] += x1v.z * mv; acc[7] += x1v.w * mv;
                }
            }
            #pragma unroll 1
            for (; il < len; ++il) {
                float mv = mu[(ic + il) * CDIM + o];
                musq += mv * mv;
                const float4* xp = (const float4*)(sm + (il << 3));
                float4 x0 = xp[0], x1v = xp[1];
                acc[0] += x0.x  * mv; acc[1] += x0.y  * mv;
                acc[2] += x0.z  * mv; acc[3] += x0.w  * mv;
                acc[4] += x1v.x * mv; acc[5] += x1v.y * mv;
                acc[6] += x1v.z * mv; acc[7] += x1v.w * mv;
            }
            __syncthreads();
        }
        #pragma unroll
        for (int k = 0; k < BT; ++k)
            g_gemm[(b0 + k) * CDIM + o] = acc[k];

        // mu^2 partial (bt==0 blocks cover mu exactly once)
        if (bt == 0) {
            for (int off = 16; off; off >>= 1)
                musq += __shfl_down_sync(0xffffffffu, musq, off);
            __syncthreads();
            if ((tid & 31) == 0) sm[tid >> 5] = musq;
            __syncthreads();
            if (tid == 0) {
                float v = 0.f;
                #pragma unroll
                for (int w = 0; w < 8; ++w) v += sm[w];
                g_red[ot] = v;
            }
        }

        // publish + count the 8 batch rows this block completed
        __threadfence();
        __syncthreads();
        if (tid == 0) {
            unsigned int m = 0;
            #pragma unroll
            for (int k = 0; k < BT; ++k) {
                unsigned int old = atomicAdd(&g_cnt[b0 + k], 1u);
                if ((old + 1u) % TARGET == 0u) m |= (1u << k);
            }
            s_mask = m;
        }
        __syncthreads();
        {
            unsigned int m = s_mask;
            if (m) {
                __threadfence();
                #pragma unroll 1
                for (int k = 0; k < BT; ++k)
                    if ((m >> k) & 1u) write_h(b0 + k, tid, lv_out, out);
            }
        }

        // D_KL: last of the 4 bt==0 blocks finalizes
        if (bt == 0) {
            if (tid == 0) {
                unsigned int old2 = atomicAdd(&g_cnt2, 1u);
                s_flag = (((old2 + 1u) & 3u) == 0u) ? 1u : 0u;
            }
            __syncthreads();
            if (s_flag) {
                __threadfence();
                float svr = 0.f, slvi = 0.f, svc = 0.f, slvo = 0.f;
                for (int i = tid; i < RDIM; i += 256) {
                    float v = lv_in[i];
                    svr  += __expf(v);
                    slvi += v;
                }
                for (int i = tid; i < CDIM; i += 256) {
                    float v = lv_out[i];
                    svc  += __expf(v);
                    slvo += v;
                }
                float vals[4] = {svr, slvi, svc, slvo};
                __syncthreads();
                #pragma unroll
                for (int k = 0; k < 4; ++k) {
                    float v = vals[k];
                    for (int off = 16; off; off >>= 1)
                        v += __shfl_down_sync(0xffffffffu, v, off);
                    if ((tid & 31) == 0) sm[k * 8 + (tid >> 5)] = v;
                }
                __syncthreads();
                if (tid == 0) {
                    float tot[4];
                    #pragma unroll
                    for (int k = 0; k < 4; ++k) {
                        float v = 0.f;
                        #pragma unroll
                        for (int w = 0; w < 8; ++w) v += sm[k * 8 + w];
                        tot[k] = v;
                    }
                    float musq_t = g_red[0] + g_red[1] + g_red[2] + g_red[3];
                    float dkl = 0.5f * (tot[0] * tot[2] + musq_t
                                        - (float)RDIM * (float)CDIM
                                        - (float)CDIM * tot[1]
                                        - (float)RDIM * tot[3]);
                    out[MB * CDIM] = dkl;
                }
            }
        }
    } else {
        // ================= E-stream role =================
        const int eid   = bid - NGEMM;
        const int b     = eid >> 3;
        const int chunk = eid & 7;
        const int i0 = (chunk * RDIM) / NSPLIT;
        const int i1 = ((chunk + 1) * RDIM) / NSPLIT;
        const int n  = i1 - i0;                       // 128 or 129

        // a[i] = x1[b,i0+i] * exp(0.5*lv_in[i0+i])
        #pragma unroll 1
        for (int idx = tid; idx < n; idx += 256) {
            int gi = i0 + idx;
            float xv = (gi < CDIM) ? x[b * CDIM + gi] : 1.0f;
            sm[idx] = xv * __expf(0.5f * lv_in[gi]);
        }
        __syncthreads();

        const float4* __restrict__ Ep =
            (const float4*)(E + (long long)b * (RDIM * CDIM)
                              + (long long)i0 * CDIM) + tid;

        float4 c0 = make_float4(0.f, 0.f, 0.f, 0.f);
        float4 c1 = c0;

        const int m = n & ~1;          // even part
        if (n & 1) {                   // peel the odd last row
            float4 e = __ldcs(Ep + m * 256);
            float a = sm[m];
            c0.x += a * e.x; c0.y += a * e.y; c0.z += a * e.z; c0.w += a * e.w;
        }

        // 2-row double-buffered stream over m rows
        float4 e0 = __ldcs(Ep);
        float4 e1 = __ldcs(Ep + 256);
        int i = 0;
        #pragma unroll 1
        for (; i + 2 < m; i += 2) {
            const float4* En = Ep + 512;
            float4 f0 = __ldcs(En);          // next pair in flight
            float4 f1 = __ldcs(En + 256);
            float a0 = sm[i], a1 = sm[i + 1];
            c0.x += a0*e0.x; c0.y += a0*e0.y; c0.z += a0*e0.z; c0.w += a0*e0.w;
            c1.x += a1*e1.x; c1.y += a1*e1.y; c1.z += a1*e1.z; c1.w += a1*e1.w;
            e0 = f0; e1 = f1; Ep = En;
        }
        {   // last buffered pair
            float a0 = sm[i], a1 = sm[i + 1];
            c0.x += a0*e0.x; c0.y += a0*e0.y; c0.z += a0*e0.z; c0.w += a0*e0.w;
            c1.x += a1*e1.x; c1.y += a1*e1.y; c1.z += a1*e1.z; c1.w += a1*e1.w;
        }

        float4 r;
        r.x = c0.x + c1.x; r.y = c0.y + c1.y;
        r.z = c0.z + c1.z; r.w = c0.w + c1.w;
        *(float4*)(g_part + (long long)eid * CDIM + (tid << 2)) = r;

        // publish + count; last of 12 writers emits h[b,:]
        __threadfence();
        __syncthreads();
        if (tid == 0) {
            unsigned int old = atomicAdd(&g_cnt[b], 1u);
            s_flag = ((old + 1u) % TARGET == 0u) ? 1u : 0u;
        }
        __syncthreads();
        if (s_flag) {
            __threadfence();
            write_h(b, tid, lv_out, out);
        }
    }
}

// -------------------------------------------------------------------------
extern "C" void kernel_launch(void* const* d_in, const int* in_sizes, int n_in,
                              void* d_out, int out_size)
{
    const float* x      = (const float*)d_in[0];   // (256, 1024)
    const float* mu     = (const float*)d_in[1];   // (1025, 1024)
    const float* lv_in  = (const float*)d_in[2];   // (1025,)
    const float* lv_out = (const float*)d_in[3];   // (1024,)
    const float* E      = (const float*)d_in[4];   // (256, 1025, 1024)
    float* out = (float*)d_out;                    // (256*1024 h) + 1 scalar

    k_all<<<NGEMM + MB * NSPLIT, 256>>>(E, mu, x, lv_in, lv_out, out);
}